// round 17
// baseline (speedup 1.0000x reference)
#include <cuda_runtime.h>
#include <cuda_fp16.h>
#include <math.h>

#define C   128
#define HW  1024
#define N   4096
#define K   128
#define INV_TEMP (1.0f/0.07f)

// Scratch: normalized row-major [N, C] fp16 features (1 MB each) + positive
// logits (fp32, logit units) computed in the normalize pass.
__device__ __align__(16) __half g_qh[N * C];
__device__ __align__(16) __half g_kh[N * C];
__device__ float g_lpos[N];

// One block per (batch b, 16-wide hw chunk): 4*64 = 256 blocks, 256 threads
// (fills 148 SMs; the previous 128-block grid left 20 SMs idle).
// Both q and k tiles live in smem, so the positive logit
// l_pos = (q/||q||)·(k/||k||) is computed here in fp32 for free.
__global__ void normalize_kernel(const float* __restrict__ fq,
                                 const float* __restrict__ fk,
                                 float* __restrict__ out) {
    __shared__ float sQ[C][17];
    __shared__ float sK[C][17];
    __shared__ float psq[16][16];
    __shared__ float psk[16][16];
    __shared__ float psd[16][16];
    __shared__ float invq[16], invk[16];

    if (blockIdx.x == 0 && threadIdx.x == 0) out[0] = 0.0f;

    const int b   = blockIdx.x >> 6;
    const int hw0 = (blockIdx.x & 63) << 4;
    const int t   = threadIdx.x;

    const float* srcq = fq + (size_t)b * C * HW + hw0;
    const float* srck = fk + (size_t)b * C * HW + hw0;

    // Load both C x 16 tiles, hw fastest (coalesced 64B per 16-lane group).
    #pragma unroll
    for (int iter = 0; iter < 8; iter++) {
        int e = t + iter * 256;
        int c = e >> 4, i = e & 15;
        sQ[c][i] = srcq[c * HW + i];
        sK[c][i] = srck[c * HW + i];
    }
    __syncthreads();

    // Partials over channels: sumsq(q), sumsq(k), dot(q,k) per hw position.
    {
        const int i = t & 15, c0 = t >> 4;
        float aq = 0.0f, ak = 0.0f, ad = 0.0f;
        #pragma unroll
        for (int c = c0; c < C; c += 16) {
            const float qv = sQ[c][i];
            const float kv = sK[c][i];
            aq += qv * qv;
            ak += kv * kv;
            ad += qv * kv;
        }
        psq[c0][i] = aq;
        psk[c0][i] = ak;
        psd[c0][i] = ad;
    }
    __syncthreads();
    if (t < 16) {
        float sq = 0.0f, sk = 0.0f, sd = 0.0f;
        #pragma unroll
        for (int r = 0; r < 16; r++) {
            sq += psq[r][t];
            sk += psk[r][t];
            sd += psd[r][t];
        }
        const float iq = 1.0f / fmaxf(sqrtf(sq), 1e-12f);
        const float ik = 1.0f / fmaxf(sqrtf(sk), 1e-12f);
        invq[t] = iq;
        invk[t] = ik;
        g_lpos[b * HW + hw0 + t] = sd * iq * ik * INV_TEMP;  // fp32-exact
    }
    __syncthreads();

    // Write transposed normalized fp16 rows (coalesced over c).
    const size_t base = ((size_t)b * HW + hw0) * C;
    #pragma unroll
    for (int iter = 0; iter < 8; iter++) {
        int e  = t + iter * 256;
        int ii = e >> 7, c = e & 127;
        g_qh[base + ii * C + c] = __float2half(sQ[c][ii] * invq[ii]);
        g_kh[base + ii * C + c] = __float2half(sK[c][ii] * invk[ii]);
    }
}

// Lane-local 16-element partial dot: one HFMA2 chain over 8 half2.
__device__ __forceinline__ float dot16h(const uint4& qv0, const uint4& qv1,
                                        const uint4& kv0, const uint4& kv1) {
    const __half2* q = reinterpret_cast<const __half2*>(&qv0);
    const __half2* Q = reinterpret_cast<const __half2*>(&qv1);
    const __half2* k = reinterpret_cast<const __half2*>(&kv0);
    const __half2* Kk = reinterpret_cast<const __half2*>(&kv1);
    __half2 acc = __hmul2(q[0], k[0]);
    acc = __hfma2(q[1], k[1], acc);
    acc = __hfma2(q[2], k[2], acc);
    acc = __hfma2(q[3], k[3], acc);
    acc = __hfma2(Q[0], Kk[0], acc);
    acc = __hfma2(Q[1], Kk[1], acc);
    acc = __hfma2(Q[2], Kk[2], acc);
    acc = __hfma2(Q[3], Kk[3], acc);
    const float2 f = __half22float2(acc);
    return f.x + f.y;
}

// 8-lane-group all-reduce on a fully converged warp: xor 4/2/1 stay inside
// the 8-lane group; every lane ends with its group's sum. Full mask.
__device__ __forceinline__ float group8_allsum(float p) {
    p += __shfl_xor_sync(0xffffffffu, p, 4);
    p += __shfl_xor_sync(0xffffffffu, p, 2);
    p += __shfl_xor_sync(0xffffffffu, p, 1);
    return p;
}

// FOUR warps per row, TWO rows per 256-thr block (grid 2048). Positive is
// handled in normalize, so pnce is perfectly uniform: 128 negatives =
// 4 warps x 4 trips x 8 slots. Warp qw covers slots [32qw, 32qw+32).
// unroll 2: trip T+1's four LDG.128 issue during trip T's compute, doubling
// in-flight gathers per warp. Online exp-sum (|logit| <= 1/0.07 ->
// fp32-exact, no max pass). All shfls full-mask on converged warps.
__global__ __launch_bounds__(256) void pnce_kernel(
        const int* __restrict__ negi, float* __restrict__ out) {
    __shared__ int   sidx[2][128];
    __shared__ float spart[2][4];

    const int t    = threadIdx.x;
    const int w    = t >> 5;
    const int lane = t & 31;
    const int r    = w >> 2;        // row within block: 0/1
    const int qw   = w & 3;         // warp within row: 0..3
    const int g    = lane >> 3;     // group 0..3
    const int l8   = lane & 7;      // lane within group
    const int n    = (blockIdx.x << 1) + r;

    // Combiner thread kicks off its lpos load early (latency hidden).
    float lpos = 0.0f;
    if (qw == 0 && lane == 0) lpos = g_lpos[n];

    // Stage this warp's 32 negative indices (coalesced).
    sidx[r][32 * qw + lane] = negi[n * K + 32 * qw + lane];
    __syncwarp();

    const uint4* qptr = reinterpret_cast<const uint4*>(g_qh + (size_t)n * C);
    const uint4 qv0 = qptr[l8];
    const uint4 qv1 = qptr[l8 + 8];

    // Lane's byte base into the key table; row offset = idx << 8.
    const char* kb = reinterpret_cast<const char*>(g_kh) + l8 * 16;

    float s = 0.0f;

    #pragma unroll 2
    for (int T = 0; T < 4; T++) {
        const int j1 = 32 * qw + T * 8 + g;
        const int i1 = sidx[r][j1];
        const int i2 = sidx[r][j1 + 4];

        const uint4* p1 =
            reinterpret_cast<const uint4*>(kb + ((size_t)(unsigned)i1 << 8));
        const uint4* p2 =
            reinterpret_cast<const uint4*>(kb + ((size_t)(unsigned)i2 << 8));
        const uint4 a0 = p1[0];
        const uint4 a1 = p1[8];     // +128 bytes
        const uint4 b0 = p2[0];
        const uint4 b1 = p2[8];

        const float d1 = group8_allsum(dot16h(qv0, qv1, a0, a1));
        const float d2 = group8_allsum(dot16h(qv0, qv1, b0, b1));

        s += __expf(d1 * INV_TEMP) + __expf(d2 * INV_TEMP);
    }

    // Cross-group combine (groups hold identical sums; each counted once).
    s += __shfl_xor_sync(0xffffffffu, s, 8);
    s += __shfl_xor_sync(0xffffffffu, s, 16);
    if (lane == 0) spart[r][qw] = s;
    __syncthreads();

    if (qw == 0 && lane == 0) {
        const float total = spart[r][0] + spart[r][1] + spart[r][2]
                          + spart[r][3] + __expf(lpos);
        atomicAdd(out, (__logf(total) - lpos) * (1.0f / (float)N));
    }
}

extern "C" void kernel_launch(void* const* d_in, const int* in_sizes, int n_in,
                              void* d_out, int out_size) {
    const float* feat_q = (const float*)d_in[0];
    const float* feat_k = (const float*)d_in[1];
    const int*   negi   = (const int*)d_in[2];
    float*       out    = (float*)d_out;

    normalize_kernel<<<256, 256>>>(feat_q, feat_k, out);
    pnce_kernel<<<N / 2, 256>>>(negi, out);
}